// round 7
// baseline (speedup 1.0000x reference)
#include <cuda_runtime.h>
#include <cuda_bf16.h>

#define NF       2048
#define NROWS    8192
#define TOTQ     (NROWS * (NF / 4))   // total float4s = 4194304
#define GRID     296                  // 2 CTAs/SM on 148 SMs: all co-resident
#define TPB      512                  // 32 warps/SM resident
#define NTHREADS (GRID * TPB)         // 151552 = 296 * 512 (multiple of row = 512 float4)
#define NPART    (NTHREADS / 512)     // 296 partials per column-quad
#define FULLIT   27                   // TOTQ / NTHREADS
#define REM      (TOTQ - FULLIT * NTHREADS)   // 102400

// Scratch (allocation-free)
__device__ float4 g_ps[NTHREADS];     // per-thread partial sums   (2.4 MB)
__device__ float4 g_pq[NTHREADS];     // per-thread partial sumsqs (2.4 MB)
__device__ float  g_mean[NF];
__device__ float  g_istd[NF];

// Self-resetting sense-reversing grid barrier (graph-replay safe).
__device__ unsigned          g_count = 0;
__device__ volatile unsigned g_sense = 0;

__device__ __forceinline__ void grid_sync() {
    __threadfence();
    __syncthreads();
    if (threadIdx.x == 0) {
        const unsigned old = g_sense;
        if (atomicAdd(&g_count, 1u) == GRID - 1) {
            g_count = 0;
            __threadfence();
            g_sense = old + 1;
        } else {
            while (g_sense == old) { __nanosleep(64); }
        }
        __threadfence();
    }
    __syncthreads();
}

__device__ __forceinline__ void acc8(float4& s, float4& q, const float4 v) {
    s.x += v.x;       s.y += v.y;       s.z += v.z;       s.w += v.w;
    q.x += v.x * v.x; q.y += v.y * v.y; q.z += v.z * v.z; q.w += v.w * v.w;
}

__global__ void __launch_bounds__(TPB, 2) k_fused(const float* __restrict__ x,
                                                  float* __restrict__ out) {
    const int tid  = blockIdx.x * TPB + threadIdx.x;   // [0, 151552)
    const int lane = threadIdx.x & 31;

    // ---------------- Phase 1: per-thread partial sum/sumsq -----------------
    // Stride NTHREADS is a multiple of the 512-float4 row -> this thread's
    // column-quad (tid & 511) is FIXED. Default policy keeps x in L2 (64 MiB).
    {
        const float4* xp = reinterpret_cast<const float4*>(x);
        float4 s = make_float4(0.f, 0.f, 0.f, 0.f);
        float4 q = make_float4(0.f, 0.f, 0.f, 0.f);
        size_t i = (size_t)tid;

        #pragma unroll 1
        for (int b = 0; b < 4; ++b) {              // 4 x 6 = 24 iters
            float4 buf[6];
            #pragma unroll
            for (int r = 0; r < 6; ++r) buf[r] = xp[i + (size_t)r * NTHREADS];
            #pragma unroll
            for (int r = 0; r < 6; ++r) acc8(s, q, buf[r]);
            i += (size_t)6 * NTHREADS;
        }
        {                                          // iters 24..26
            float4 buf[3];
            #pragma unroll
            for (int r = 0; r < 3; ++r) buf[r] = xp[i + (size_t)r * NTHREADS];
            #pragma unroll
            for (int r = 0; r < 3; ++r) acc8(s, q, buf[r]);
            i += (size_t)3 * NTHREADS;
        }
        if (tid < REM) acc8(s, q, xp[i]);          // ragged 28th iter

        g_ps[tid] = s;
        g_pq[tid] = q;
    }

    grid_sync();

    // ---------------- Phase 2: one warp per column-quad ---------------------
    // Quad qd has partials at g_ps[qd + 512*k], k in [0,296). Butterfly
    // shuffle reduce: fixed tree, deterministic. Scratch is L2-hot (4.8 MB).
    {
        const int gw = tid >> 5;                   // global warp id
        if (gw < NF / 4) {
            float4 S = make_float4(0.f, 0.f, 0.f, 0.f);
            float4 Q = make_float4(0.f, 0.f, 0.f, 0.f);
            for (int k = lane; k < NPART; k += 32) {
                const float4 a = g_ps[gw + (k << 9)];
                const float4 b = g_pq[gw + (k << 9)];
                S.x += a.x; S.y += a.y; S.z += a.z; S.w += a.w;
                Q.x += b.x; Q.y += b.y; Q.z += b.z; Q.w += b.w;
            }
            #pragma unroll
            for (int o = 16; o > 0; o >>= 1) {
                S.x += __shfl_xor_sync(0xffffffffu, S.x, o);
                S.y += __shfl_xor_sync(0xffffffffu, S.y, o);
                S.z += __shfl_xor_sync(0xffffffffu, S.z, o);
                S.w += __shfl_xor_sync(0xffffffffu, S.w, o);
                Q.x += __shfl_xor_sync(0xffffffffu, Q.x, o);
                Q.y += __shfl_xor_sync(0xffffffffu, Q.y, o);
                Q.z += __shfl_xor_sync(0xffffffffu, Q.z, o);
                Q.w += __shfl_xor_sync(0xffffffffu, Q.w, o);
            }
            if (lane < 4) {
                const float sv = lane == 0 ? S.x : lane == 1 ? S.y : lane == 2 ? S.z : S.w;
                const float qv = lane == 0 ? Q.x : lane == 1 ? Q.y : lane == 2 ? Q.z : Q.w;
                const double mean = (double)sv / (double)NROWS;
                const double var  = ((double)qv - (double)sv * mean) / (double)(NROWS - 1);
                g_mean[gw * 4 + lane] = (float)mean;
                g_istd[gw * 4 + lane] = (float)(1.0 / sqrt(var + 1e-6));
            }
        }
    }

    grid_sync();

    // ---------------- Phase 3: normalize ------------------------------------
    // Same fixed-column striding -> mean/istd loaded ONCE per thread.
    // __ldcs: last use of x (evict-first). __stcs: out won't be re-read.
    {
        const int qd = tid & 511;
        const float4 m = *reinterpret_cast<const float4*>(g_mean + 4 * qd);
        const float4 t = *reinterpret_cast<const float4*>(g_istd + 4 * qd);
        const float4* xp = reinterpret_cast<const float4*>(x);
        float4*       op = reinterpret_cast<float4*>(out);
        size_t i = (size_t)tid;

        #pragma unroll 1
        for (int b = 0; b < 4; ++b) {
            float4 buf[6];
            #pragma unroll
            for (int r = 0; r < 6; ++r) buf[r] = __ldcs(xp + i + (size_t)r * NTHREADS);
            #pragma unroll
            for (int r = 0; r < 6; ++r) {
                float4 o;
                o.x = (buf[r].x - m.x) * t.x;  o.y = (buf[r].y - m.y) * t.y;
                o.z = (buf[r].z - m.z) * t.z;  o.w = (buf[r].w - m.w) * t.w;
                __stcs(op + i + (size_t)r * NTHREADS, o);
            }
            i += (size_t)6 * NTHREADS;
        }
        {
            float4 buf[3];
            #pragma unroll
            for (int r = 0; r < 3; ++r) buf[r] = __ldcs(xp + i + (size_t)r * NTHREADS);
            #pragma unroll
            for (int r = 0; r < 3; ++r) {
                float4 o;
                o.x = (buf[r].x - m.x) * t.x;  o.y = (buf[r].y - m.y) * t.y;
                o.z = (buf[r].z - m.z) * t.z;  o.w = (buf[r].w - m.w) * t.w;
                __stcs(op + i + (size_t)r * NTHREADS, o);
            }
            i += (size_t)3 * NTHREADS;
        }
        if (tid < REM) {
            const float4 v = __ldcs(xp + i);
            float4 o;
            o.x = (v.x - m.x) * t.x;  o.y = (v.y - m.y) * t.y;
            o.z = (v.z - m.z) * t.z;  o.w = (v.w - m.w) * t.w;
            __stcs(op + i, o);
        }
    }
}

extern "C" void kernel_launch(void* const* d_in, const int* in_sizes, int n_in,
                              void* d_out, int out_size) {
    const float* x = (const float*)d_in[0];   // [8192, 2048] fp32
    float* out = (float*)d_out;               // [8192, 2048] fp32
    k_fused<<<GRID, TPB>>>(x, out);
}

// round 8
// speedup vs baseline: 1.1656x; 1.1656x over previous
#include <cuda_runtime.h>
#include <cuda_bf16.h>

#define NF      2048
#define NROWS   8192
#define RCHUNKS 512
#define RPC     (NROWS / RCHUNKS)   // 16 rows per chunk

// Scratch (allocation-free): partial sums/sumsqs + final stats
__device__ float g_psum[RCHUNKS * NF];   // 4 MiB
__device__ float g_psq [RCHUNKS * NF];   // 4 MiB
__device__ float g_mean[NF];
__device__ float g_istd[NF];

// ---------------------------------------------------------------------------
// Pass 1 (exact R3 version: regs=31, occ=77%, best measured 13.7us).
// Each block = (1024 columns) x (16 rows); grid (2, 512).
// ---------------------------------------------------------------------------
__global__ void __launch_bounds__(256) k_partial(const float* __restrict__ x) {
    const int col   = (blockIdx.x * 256 + threadIdx.x) * 4;
    const int chunk = blockIdx.y;
    const float4* xp = reinterpret_cast<const float4*>(
        x + (size_t)chunk * RPC * NF + col);

    float4 s = make_float4(0.f, 0.f, 0.f, 0.f);
    float4 q = make_float4(0.f, 0.f, 0.f, 0.f);
    #pragma unroll
    for (int r = 0; r < RPC; ++r) {
        float4 v = xp[(size_t)r * (NF / 4)];   // default policy: x stays in L2
        s.x += v.x;       s.y += v.y;       s.z += v.z;       s.w += v.w;
        q.x += v.x * v.x; q.y += v.y * v.y; q.z += v.z * v.z; q.w += v.w * v.w;
    }
    *reinterpret_cast<float4*>(g_psum + chunk * NF + col) = s;
    *reinterpret_cast<float4*>(g_psq  + chunk * NF + col) = q;
}

// ---------------------------------------------------------------------------
// Pass 2: 128 blocks x 256 threads; 16 cols/block, 16 threads/col x 32
// partials each (coalesced, L2-hot), fixed-order shared combine.
// PDL: trigger at entry so k_norm can start its x preamble; sync before
// reading partials (waits for k_partial completion).
// var = (sumsq - N*mean^2)/(N-1)  (ddof=1, matches sequential Welford).
// ---------------------------------------------------------------------------
__global__ void __launch_bounds__(256) k_finish() {
    cudaTriggerProgrammaticLaunchCompletion();
    cudaGridDependencySynchronize();

    __shared__ float ssum[256];
    __shared__ float ssq [256];
    const int t  = threadIdx.x;
    const int cl = t & 15;
    const int j  = t >> 4;
    const int c  = blockIdx.x * 16 + cl;

    float s = 0.f, q = 0.f;
    #pragma unroll 8
    for (int k = j * 32; k < j * 32 + 32; ++k) {
        s += g_psum[k * NF + c];
        q += g_psq [k * NF + c];
    }
    ssum[t] = s;
    ssq [t] = q;
    __syncthreads();

    if (j == 0) {
        double S = 0.0, Q = 0.0;
        #pragma unroll
        for (int jj = 0; jj < 16; ++jj) {
            S += (double)ssum[jj * 16 + cl];
            Q += (double)ssq [jj * 16 + cl];
        }
        const double mean = S / (double)NROWS;
        const double var  = (Q - S * mean) / (double)(NROWS - 1);
        g_mean[c] = (float)mean;
        g_istd[c] = (float)(1.0 / sqrt(var + 1e-6));
    }
}

// ---------------------------------------------------------------------------
// Pass 3: out = (x - mean[col]) * istd[col]. ILP=4, stride 1M float4s
// (multiple of the 512-float4 row -> fixed column quad per thread).
// PDL: x loads are independent of upstream, so issue them BEFORE the
// dependency sync -> first-wave x reads overlap k_finish + launch gap.
// __ldcs: last use of x (evict-first). __stcs: out won't be re-read.
// ---------------------------------------------------------------------------
#define NORM_T  (NROWS * (NF / 4) / 4)   // 1048576 threads, 4 float4 each

__global__ void __launch_bounds__(256) k_norm(const float* __restrict__ x,
                                              float* __restrict__ out) {
    const size_t t   = (size_t)blockIdx.x * 256 + threadIdx.x;  // [0, NORM_T)
    const int    col = (int)((t * 4) & (NF - 1));
    const float4* xp = reinterpret_cast<const float4*>(x);
    float4*       op = reinterpret_cast<float4*>(out);

    float4 v0 = __ldcs(xp + t);
    float4 v1 = __ldcs(xp + t + (size_t)NORM_T);
    float4 v2 = __ldcs(xp + t + (size_t)2 * NORM_T);
    float4 v3 = __ldcs(xp + t + (size_t)3 * NORM_T);

    cudaGridDependencySynchronize();   // wait for k_finish's g_mean/g_istd

    const float4 m = *reinterpret_cast<const float4*>(g_mean + col);
    const float4 r = *reinterpret_cast<const float4*>(g_istd + col);

    float4 o0, o1, o2, o3;
    o0.x = (v0.x - m.x) * r.x;  o0.y = (v0.y - m.y) * r.y;
    o0.z = (v0.z - m.z) * r.z;  o0.w = (v0.w - m.w) * r.w;
    o1.x = (v1.x - m.x) * r.x;  o1.y = (v1.y - m.y) * r.y;
    o1.z = (v1.z - m.z) * r.z;  o1.w = (v1.w - m.w) * r.w;
    o2.x = (v2.x - m.x) * r.x;  o2.y = (v2.y - m.y) * r.y;
    o2.z = (v2.z - m.z) * r.z;  o2.w = (v2.w - m.w) * r.w;
    o3.x = (v3.x - m.x) * r.x;  o3.y = (v3.y - m.y) * r.y;
    o3.z = (v3.z - m.z) * r.z;  o3.w = (v3.w - m.w) * r.w;

    __stcs(op + t,                      o0);
    __stcs(op + t + (size_t)NORM_T,     o1);
    __stcs(op + t + (size_t)2 * NORM_T, o2);
    __stcs(op + t + (size_t)3 * NORM_T, o3);
}

extern "C" void kernel_launch(void* const* d_in, const int* in_sizes, int n_in,
                              void* d_out, int out_size) {
    const float* x = (const float*)d_in[0];   // [8192, 2048] fp32
    float* out = (float*)d_out;               // [8192, 2048] fp32

    k_partial<<<dim3(NF / 1024, RCHUNKS), 256>>>(x);

    cudaLaunchAttribute pdl;
    pdl.id = cudaLaunchAttributeProgrammaticStreamSerialization;
    pdl.val.programmaticStreamSerializationAllowed = 1;

    {
        cudaLaunchConfig_t cfg = {};
        cfg.gridDim  = dim3(NF / 16);
        cfg.blockDim = dim3(256);
        cfg.attrs    = &pdl;
        cfg.numAttrs = 1;
        cfg.stream   = 0;
        cudaLaunchKernelEx(&cfg, k_finish);
    }
    {
        cudaLaunchConfig_t cfg = {};
        cfg.gridDim  = dim3(NORM_T / 256);
        cfg.blockDim = dim3(256);
        cfg.attrs    = &pdl;
        cfg.numAttrs = 1;
        cfg.stream   = 0;
        cudaLaunchKernelEx(&cfg, k_norm, x, out);
    }
}

// round 11
// speedup vs baseline: 1.1741x; 1.0073x over previous
#include <cuda_runtime.h>
#include <cuda_bf16.h>

#define NF      2048
#define NROWS   8192
#define RCHUNKS 512
#define RPC     (NROWS / RCHUNKS)   // 16 rows per chunk

// Scratch (allocation-free): partial sums/sumsqs + final stats
__device__ float g_psum[RCHUNKS * NF];   // 4 MiB
__device__ float g_psq [RCHUNKS * NF];   // 4 MiB
__device__ float g_mean[NF];
__device__ float g_istd[NF];

// ---------------------------------------------------------------------------
// Pass 1 (R3 body: regs=31, occ=76%). Early PDL trigger at entry so the
// downstream kernels PRELAUNCH and their preambles overlap this kernel's
// tail. Their cudaGridDependencySynchronize still waits for our completion.
// ---------------------------------------------------------------------------
__global__ void __launch_bounds__(256) k_partial(const float* __restrict__ x) {
    cudaTriggerProgrammaticLaunchCompletion();

    const int col   = (blockIdx.x * 256 + threadIdx.x) * 4;
    const int chunk = blockIdx.y;
    const float4* xp = reinterpret_cast<const float4*>(
        x + (size_t)chunk * RPC * NF + col);

    float4 s = make_float4(0.f, 0.f, 0.f, 0.f);
    float4 q = make_float4(0.f, 0.f, 0.f, 0.f);
    #pragma unroll
    for (int r = 0; r < RPC; ++r) {
        float4 v = xp[(size_t)r * (NF / 4)];   // default policy: x stays in L2
        s.x += v.x;       s.y += v.y;       s.z += v.z;       s.w += v.w;
        q.x += v.x * v.x; q.y += v.y * v.y; q.z += v.z * v.z; q.w += v.w * v.w;
    }
    *reinterpret_cast<float4*>(g_psum + chunk * NF + col) = s;
    *reinterpret_cast<float4*>(g_psq  + chunk * NF + col) = q;
}

// ---------------------------------------------------------------------------
// Pass 2: 128 blocks x 256 threads; 16 cols/block, 16 threads/col x 32
// partials each (coalesced, L2-hot), fixed-order shared combine.
// PDL: trigger at entry (so k_norm prelaunches); sync before reading
// partials (waits for k_partial completion).
// var = (sumsq - N*mean^2)/(N-1)  (ddof=1, matches sequential Welford).
// ---------------------------------------------------------------------------
__global__ void __launch_bounds__(256) k_finish() {
    cudaTriggerProgrammaticLaunchCompletion();
    cudaGridDependencySynchronize();

    __shared__ float ssum[256];
    __shared__ float ssq [256];
    const int t  = threadIdx.x;
    const int cl = t & 15;
    const int j  = t >> 4;
    const int c  = blockIdx.x * 16 + cl;

    float s = 0.f, q = 0.f;
    #pragma unroll 8
    for (int k = j * 32; k < j * 32 + 32; ++k) {
        s += g_psum[k * NF + c];
        q += g_psq [k * NF + c];
    }
    ssum[t] = s;
    ssq [t] = q;
    __syncthreads();

    if (j == 0) {
        double S = 0.0, Q = 0.0;
        #pragma unroll
        for (int jj = 0; jj < 16; ++jj) {
            S += (double)ssum[jj * 16 + cl];
            Q += (double)ssq [jj * 16 + cl];
        }
        const double mean = S / (double)NROWS;
        const double var  = (Q - S * mean) / (double)(NROWS - 1);
        g_mean[c] = (float)mean;
        g_istd[c] = (float)(1.0 / sqrt(var + 1e-6));
    }
}

// ---------------------------------------------------------------------------
// Pass 3: out = (x - mean[col]) * istd[col]. ILP=4, stride NORM_T float4s
// (multiple of the 512-float4 row -> fixed column quad per thread).
// ALL x reads are in the pre-sync preamble: they overlap k_partial's tail /
// k_finish via PDL prelaunch, and hit L2 (populated by k_partial).
// __ldcs: last use of x (evict-first). __stcs: out won't be re-read.
// ---------------------------------------------------------------------------
#define NORM_T  (NROWS * (NF / 4) / 4)   // 1048576 threads, 4 float4 each

__global__ void __launch_bounds__(256) k_norm(const float* __restrict__ x,
                                              float* __restrict__ out) {
    const size_t t   = (size_t)blockIdx.x * 256 + threadIdx.x;  // [0, NORM_T)
    const int    col = (int)((t * 4) & (NF - 1));
    const float4* xp = reinterpret_cast<const float4*>(x);
    float4*       op = reinterpret_cast<float4*>(out);

    float4 v0 = __ldcs(xp + t);
    float4 v1 = __ldcs(xp + t + (size_t)NORM_T);
    float4 v2 = __ldcs(xp + t + (size_t)2 * NORM_T);
    float4 v3 = __ldcs(xp + t + (size_t)3 * NORM_T);

    cudaGridDependencySynchronize();   // wait for k_finish's g_mean/g_istd

    const float4 m = *reinterpret_cast<const float4*>(g_mean + col);
    const float4 r = *reinterpret_cast<const float4*>(g_istd + col);

    float4 o0, o1, o2, o3;
    o0.x = (v0.x - m.x) * r.x;  o0.y = (v0.y - m.y) * r.y;
    o0.z = (v0.z - m.z) * r.z;  o0.w = (v0.w - m.w) * r.w;
    o1.x = (v1.x - m.x) * r.x;  o1.y = (v1.y - m.y) * r.y;
    o1.z = (v1.z - m.z) * r.z;  o1.w = (v1.w - m.w) * r.w;
    o2.x = (v2.x - m.x) * r.x;  o2.y = (v2.y - m.y) * r.y;
    o2.z = (v2.z - m.z) * r.z;  o2.w = (v2.w - m.w) * r.w;
    o3.x = (v3.x - m.x) * r.x;  o3.y = (v3.y - m.y) * r.y;
    o3.z = (v3.z - m.z) * r.z;  o3.w = (v3.w - m.w) * r.w;

    __stcs(op + t,                      o0);
    __stcs(op + t + (size_t)NORM_T,     o1);
    __stcs(op + t + (size_t)2 * NORM_T, o2);
    __stcs(op + t + (size_t)3 * NORM_T, o3);
}

extern "C" void kernel_launch(void* const* d_in, const int* in_sizes, int n_in,
                              void* d_out, int out_size) {
    const float* x = (const float*)d_in[0];   // [8192, 2048] fp32
    float* out = (float*)d_out;               // [8192, 2048] fp32

    k_partial<<<dim3(NF / 1024, RCHUNKS), 256>>>(x);

    cudaLaunchAttribute pdl;
    pdl.id = cudaLaunchAttributeProgrammaticStreamSerialization;
    pdl.val.programmaticStreamSerializationAllowed = 1;

    {
        cudaLaunchConfig_t cfg = {};
        cfg.gridDim  = dim3(NF / 16);
        cfg.blockDim = dim3(256);
        cfg.attrs    = &pdl;
        cfg.numAttrs = 1;
        cfg.stream   = 0;
        cudaLaunchKernelEx(&cfg, k_finish);
    }
    {
        cudaLaunchConfig_t cfg = {};
        cfg.gridDim  = dim3(NORM_T / 256);
        cfg.blockDim = dim3(256);
        cfg.attrs    = &pdl;
        cfg.numAttrs = 1;
        cfg.stream   = 0;
        cudaLaunchKernelEx(&cfg, k_norm, x, out);
    }
}